// round 2
// baseline (speedup 1.0000x reference)
#include <cuda_runtime.h>
#include <math.h>

// Problem constants
#define NB   16384        // batch rows
#define ZLD  513          // z leading dim (2L+1)
#define XK   1024         // concat input width (2L + C)
#define HD   1024         // hidden
#define LD   256          // L
#define OUTC 513          // output cols per tensor

// Scratch (allocation-free rule: __device__ globals)
__device__ float g_X [NB * XK];   // [pm | ctx_i]    64 MB
__device__ float g_H1[NB * HD];   // tanh(pm@Wh1+bh1)  64 MB
__device__ float g_H2[NB * HD];   // tanh(X @Wc1+bc1)  64 MB
__device__ float g_P1[NB * LD];   // prior drift       16 MB
__device__ float g_P2[NB * LD];   // posterior drift   16 MB

// ---------------------------------------------------------------------------
// K0: build X = [ z[:, :512] , ctx[:, i, :] ]  with i = min(searchsorted(ts,t,'right'), T-1)
// ---------------------------------------------------------------------------
__global__ void prep_kernel(const float* __restrict__ z,
                            const float* __restrict__ ctx,
                            const float* __restrict__ ts,
                            const float* __restrict__ tp)
{
    int idx = blockIdx.x * blockDim.x + threadIdx.x;   // 0 .. NB*1024-1
    float t = tp[0];
    int i = 0;
    #pragma unroll
    for (int j = 0; j < 16; ++j) i += (ts[j] <= t) ? 1 : 0;   // side='right'
    if (i > 15) i = 15;

    int row = idx >> 10;
    int c   = idx & 1023;
    float v;
    if (c < 512) v = z[(long)row * ZLD + c];
    else         v = ctx[((long)row * 16 + i) * 512 + (c - 512)];
    g_X[idx] = v;
}

// ---------------------------------------------------------------------------
// Tiled SGEMM: C[M,N] = act(A[M,K] @ W[K,N] + bias)
// BM=BN=128, BK=8, 256 threads, 8x8 microtile, double-buffered smem.
// M multiple of 128 (grid.y), N multiple of 128 (grid.x), K multiple of 8.
// ---------------------------------------------------------------------------
__global__ __launch_bounds__(256)
void sgemm_kernel(const float* __restrict__ A, int lda,
                  const float* __restrict__ W, int N,      // ldw == N
                  const float* __restrict__ bias,
                  float* __restrict__ C, int ldc,
                  int K, int act)
{
    __shared__ float As[2][8][128];
    __shared__ float Bs[2][8][128];

    const int tid = threadIdx.x;
    const int tx  = tid & 15;     // 16 col groups
    const int ty  = tid >> 4;     // 16 row groups
    const int m0  = blockIdx.y * 128;
    const int n0  = blockIdx.x * 128;

    // Global->smem mapping
    const int a_row = tid >> 1;            // 0..127
    const int a_col = (tid & 1) << 2;      // 0 or 4
    const int b_row = tid >> 5;            // 0..7
    const int b_col = (tid & 31) << 2;     // 0..124 step 4

    const float* Ap = A + (long)(m0 + a_row) * lda + a_col;
    const float* Wp = W + (long)b_row * N + n0 + b_col;

    float acc[8][8];
    #pragma unroll
    for (int i = 0; i < 8; ++i)
        #pragma unroll
        for (int j = 0; j < 8; ++j) acc[i][j] = 0.f;

    // preload tile 0
    {
        float4 av = *reinterpret_cast<const float4*>(Ap);
        As[0][a_col + 0][a_row] = av.x;
        As[0][a_col + 1][a_row] = av.y;
        As[0][a_col + 2][a_row] = av.z;
        As[0][a_col + 3][a_row] = av.w;
        float4 bv = *reinterpret_cast<const float4*>(Wp);
        *reinterpret_cast<float4*>(&Bs[0][b_row][b_col]) = bv;
    }
    __syncthreads();

    int buf = 0;
    for (int kt = 0; kt < K; kt += 8) {
        // prefetch next K-tile into the other buffer
        if (kt + 8 < K) {
            float4 av = *reinterpret_cast<const float4*>(Ap + kt + 8);
            float4 bv = *reinterpret_cast<const float4*>(Wp + (long)(kt + 8) * N);
            int nb = buf ^ 1;
            As[nb][a_col + 0][a_row] = av.x;
            As[nb][a_col + 1][a_row] = av.y;
            As[nb][a_col + 2][a_row] = av.z;
            As[nb][a_col + 3][a_row] = av.w;
            *reinterpret_cast<float4*>(&Bs[nb][b_row][b_col]) = bv;
        }
        #pragma unroll
        for (int kk = 0; kk < 8; ++kk) {
            float ar[8], br[8];
            #pragma unroll
            for (int i = 0; i < 8; ++i) ar[i] = As[buf][kk][ty * 8 + i];
            #pragma unroll
            for (int j = 0; j < 8; ++j) br[j] = Bs[buf][kk][tx * 8 + j];
            #pragma unroll
            for (int i = 0; i < 8; ++i)
                #pragma unroll
                for (int j = 0; j < 8; ++j)
                    acc[i][j] = fmaf(ar[i], br[j], acc[i][j]);
        }
        __syncthreads();
        buf ^= 1;
    }

    // epilogue: bias + optional tanh, float4 stores
    #pragma unroll
    for (int i = 0; i < 8; ++i) {
        int m = m0 + ty * 8 + i;
        float* Crow = C + (long)m * ldc + n0 + tx * 8;
        #pragma unroll
        for (int jv = 0; jv < 2; ++jv) {
            float4 v;
            float b0 = bias[n0 + tx * 8 + jv * 4 + 0];
            float b1 = bias[n0 + tx * 8 + jv * 4 + 1];
            float b2 = bias[n0 + tx * 8 + jv * 4 + 2];
            float b3 = bias[n0 + tx * 8 + jv * 4 + 3];
            v.x = acc[i][jv * 4 + 0] + b0;
            v.y = acc[i][jv * 4 + 1] + b1;
            v.z = acc[i][jv * 4 + 2] + b2;
            v.w = acc[i][jv * 4 + 3] + b3;
            if (act) {
                v.x = tanhf(v.x); v.y = tanhf(v.y);
                v.z = tanhf(v.z); v.w = tanhf(v.w);
            }
            *reinterpret_cast<float4*>(Crow + jv * 4) = v;
        }
    }
}

// ---------------------------------------------------------------------------
// K5: per-row epilogue. One block (256 threads) per batch row.
// out[0 : NB*513]          = drift      = [inv_mass*momentum, posterior, dkl]
// out[NB*513 : 2*NB*513]   = diffusion  = [0, diffusion, 0]
// ---------------------------------------------------------------------------
__global__ void final_kernel(const float* __restrict__ z,
                             const float* __restrict__ inv_mass,
                             const float* __restrict__ diffusion,
                             float* __restrict__ out)
{
    int row = blockIdx.x;
    int j   = threadIdx.x;   // 0..255

    float p1  = g_P1[(long)row * LD + j];
    float p2  = g_P2[(long)row * LD + j];
    float dif = diffusion[j];

    // safe_divide semantics: den if |den|>EPS else sign(den)*EPS
    float sgn  = (dif > 0.f) ? 1.f : ((dif < 0.f) ? -1.f : 0.f);
    float sden = (fabsf(dif) > 1e-7f) ? dif : sgn * 1e-7f;
    float r    = (p1 - p2) / sden;
    float sq   = r * r;

    // block reduction over 256 lanes
    __shared__ float wsum[8];
    #pragma unroll
    for (int off = 16; off > 0; off >>= 1)
        sq += __shfl_down_sync(0xffffffffu, sq, off);
    if ((j & 31) == 0) wsum[j >> 5] = sq;
    __syncthreads();

    long dbase = (long)row * OUTC;
    long obase = (long)NB * OUTC + dbase;

    if (j == 0) {
        float s = 0.f;
        #pragma unroll
        for (int w = 0; w < 8; ++w) s += wsum[w];
        out[dbase + 512] = s;     // dkl_drift
        out[obase + 512] = 0.f;
    }

    float mom = z[(long)row * ZLD + 256 + j];
    out[dbase + j]       = inv_mass[j] * mom;   // position_drift
    out[dbase + 256 + j] = p2;                  // posterior drift
    out[obase + j]       = 0.f;
    out[obase + 256 + j] = dif;
}

// ---------------------------------------------------------------------------
extern "C" void kernel_launch(void* const* d_in, const int* in_sizes, int n_in,
                              void* d_out, int out_size)
{
    const float* z    = (const float*)d_in[0];
    const float* ts   = (const float*)d_in[1];
    const float* t    = (const float*)d_in[2];
    const float* ctx  = (const float*)d_in[3];
    const float* im   = (const float*)d_in[4];
    const float* dif  = (const float*)d_in[5];
    const float* Wc1  = (const float*)d_in[6];
    const float* bc1  = (const float*)d_in[7];
    const float* Wc2  = (const float*)d_in[8];
    const float* bc2  = (const float*)d_in[9];
    const float* Wh1  = (const float*)d_in[10];
    const float* bh1  = (const float*)d_in[11];
    const float* Wh2  = (const float*)d_in[12];
    const float* bh2  = (const float*)d_in[13];
    float* out = (float*)d_out;

    float *pX, *pH1, *pH2, *pP1, *pP2;
    cudaGetSymbolAddress((void**)&pX,  g_X);
    cudaGetSymbolAddress((void**)&pH1, g_H1);
    cudaGetSymbolAddress((void**)&pH2, g_H2);
    cudaGetSymbolAddress((void**)&pP1, g_P1);
    cudaGetSymbolAddress((void**)&pP2, g_P2);

    // K0: build X
    prep_kernel<<<(NB * XK) / 256, 256>>>(z, ctx, ts, t);

    // K1: H1 = tanh(pm @ Wh1 + bh1)    (K=512, A = X first 512 cols, lda=1024)
    sgemm_kernel<<<dim3(HD / 128, NB / 128), 256>>>(pX, XK, Wh1, HD, bh1, pH1, HD, 512, 1);

    // K2: H2 = tanh(X @ Wc1 + bc1)     (K=1024)
    sgemm_kernel<<<dim3(HD / 128, NB / 128), 256>>>(pX, XK, Wc1, HD, bc1, pH2, HD, 1024, 1);

    // K3: P1 = H1 @ Wh2 + bh2          (N=256)
    sgemm_kernel<<<dim3(LD / 128, NB / 128), 256>>>(pH1, HD, Wh2, LD, bh2, pP1, LD, 1024, 0);

    // K4: P2 = H2 @ Wc2 + bc2
    sgemm_kernel<<<dim3(LD / 128, NB / 128), 256>>>(pH2, HD, Wc2, LD, bc2, pP2, LD, 1024, 0);

    // K5: epilogue + output assembly
    final_kernel<<<NB, 256>>>(z, im, dif, out);
}

// round 5
// speedup vs baseline: 2.5700x; 2.5700x over previous
#include <cuda_runtime.h>
#include <cuda_bf16.h>
#include <cstdint>
#include <math.h>

// ---------------- problem constants ----------------
#define NB   16384
#define ZLD  513
#define XK   1024
#define HD   1024
#define LD   256
#define OUTC 513

// ---------------- scratch ----------------
__device__ __nv_bfloat16 g_Xh [NB * XK];
__device__ __nv_bfloat16 g_Xl [NB * XK];
__device__ __nv_bfloat16 g_H1h[NB * HD];
__device__ __nv_bfloat16 g_H1l[NB * HD];
__device__ __nv_bfloat16 g_H2h[NB * HD];
__device__ __nv_bfloat16 g_H2l[NB * HD];
__device__ float         g_P1 [NB * LD];
__device__ float         g_P2 [NB * LD];
// transposed + split weights: Wt[n*K+k] = W[k*N+n]
__device__ __nv_bfloat16 g_Wh1h[HD * 512], g_Wh1l[HD * 512];
__device__ __nv_bfloat16 g_Wc1h[HD * XK],  g_Wc1l[HD * XK];
__device__ __nv_bfloat16 g_Wh2h[LD * HD],  g_Wh2l[LD * HD];
__device__ __nv_bfloat16 g_Wc2h[LD * HD],  g_Wc2l[LD * HD];

// ---------------- helpers ----------------
__device__ __forceinline__ uint32_t smem_u32(const void* p) {
    uint32_t a;
    asm("{ .reg .u64 t; cvta.to.shared.u64 t, %1; cvt.u32.u64 %0, t; }" : "=r"(a) : "l"(p));
    return a;
}
__device__ __forceinline__ void ldsm4(uint32_t (&r)[4], uint32_t addr) {
    asm volatile("ldmatrix.sync.aligned.m8n8.x4.shared.b16 {%0,%1,%2,%3}, [%4];"
        : "=r"(r[0]), "=r"(r[1]), "=r"(r[2]), "=r"(r[3]) : "r"(addr));
}
__device__ __forceinline__ void mma16816(float (&d)[4], const uint32_t (&a)[4],
                                         uint32_t b0, uint32_t b1) {
    asm volatile("mma.sync.aligned.m16n8k16.row.col.f32.bf16.bf16.f32 "
        "{%0,%1,%2,%3}, {%4,%5,%6,%7}, {%8,%9}, {%0,%1,%2,%3};"
        : "+f"(d[0]), "+f"(d[1]), "+f"(d[2]), "+f"(d[3])
        : "r"(a[0]), "r"(a[1]), "r"(a[2]), "r"(a[3]), "r"(b0), "r"(b1));
}
__device__ __forceinline__ void cpasync16(uint32_t saddr, const void* g) {
    asm volatile("cp.async.cg.shared.global [%0], [%1], 16;" :: "r"(saddr), "l"(g));
}
__device__ __forceinline__ void cp_commit() { asm volatile("cp.async.commit_group;"); }
__device__ __forceinline__ void cp_wait1()  { asm volatile("cp.async.wait_group 1;"  ::: "memory"); }
__device__ __forceinline__ void cp_wait0()  { asm volatile("cp.async.wait_group 0;"  ::: "memory"); }

__device__ __forceinline__ void split_bf16(float v, __nv_bfloat16& hi, __nv_bfloat16& lo) {
    hi = __float2bfloat16(v);
    lo = __float2bfloat16(v - __bfloat162float(hi));
}

// ---------------------------------------------------------------------------
// K0: X = [ z[:, :512] , ctx[:, i, :] ]  split to bf16 hi/lo
// ---------------------------------------------------------------------------
__global__ void prep_kernel(const float* __restrict__ z,
                            const float* __restrict__ ctx,
                            const float* __restrict__ ts,
                            const float* __restrict__ tp)
{
    int idx = blockIdx.x * blockDim.x + threadIdx.x;
    float t = tp[0];
    int i = 0;
    #pragma unroll
    for (int j = 0; j < 16; ++j) i += (ts[j] <= t) ? 1 : 0;
    if (i > 15) i = 15;
    int row = idx >> 10, c = idx & 1023;
    float v = (c < 512) ? z[(long)row * ZLD + c]
                        : ctx[((long)row * 16 + i) * 512 + (c - 512)];
    __nv_bfloat16 hi, lo; split_bf16(v, hi, lo);
    g_Xh[idx] = hi; g_Xl[idx] = lo;
}

// ---------------------------------------------------------------------------
// Weight transpose + bf16 split: Wt[n][k] = W[k][n]
// ---------------------------------------------------------------------------
__global__ void wsplit_kernel(const float* __restrict__ W, int K, int N,
                              __nv_bfloat16* __restrict__ Th,
                              __nv_bfloat16* __restrict__ Tl)
{
    __shared__ float s[32][33];
    int k = blockIdx.y * 32 + threadIdx.y;
    int n = blockIdx.x * 32 + threadIdx.x;
    s[threadIdx.y][threadIdx.x] = W[(long)k * N + n];
    __syncthreads();
    int nn = blockIdx.x * 32 + threadIdx.y;
    int kk = blockIdx.y * 32 + threadIdx.x;
    float v = s[threadIdx.x][threadIdx.y];
    __nv_bfloat16 hi, lo; split_bf16(v, hi, lo);
    Th[(long)nn * K + kk] = hi;
    Tl[(long)nn * K + kk] = lo;
}

// ---------------------------------------------------------------------------
// mma.sync bf16 GEMM (3-term hi/lo split): C = act(A @ Wt^T + bias)
//   A : [M][lda] bf16 hi/lo,   B(=Wt) : [N][K] bf16 hi/lo
// CTA tile 128x128, BK=32, 256 thr / 8 warps (warp tile 64x32).
// Smem per stage:  A_h 8K | A_l 8K | B_h 8K | B_l 8K.
// Rows are 64B; in-row layout swizzled:  phys = logical16B ^ (((row>>1)&3)*16)
// ---------------------------------------------------------------------------
#define BK      32
#define STAGE   32768

template<int ACT>
__global__ __launch_bounds__(256, 2)
void mma_gemm(const __nv_bfloat16* __restrict__ Ah, const __nv_bfloat16* __restrict__ Al, int lda,
              const __nv_bfloat16* __restrict__ Bh, const __nv_bfloat16* __restrict__ Bl,
              const float* __restrict__ bias,
              __nv_bfloat16* __restrict__ Ch, __nv_bfloat16* __restrict__ Cl,
              float* __restrict__ Cf, int ldc, int K)
{
    extern __shared__ char smem[];
    const uint32_t sb = smem_u32(smem);
    const int tid  = threadIdx.x;
    const int wid  = tid >> 5;
    const int lane = tid & 31;
    const int wm   = wid >> 2;          // 0..1  (64-row slab)
    const int wn   = wid & 3;           // 0..3  (32-col slab)
    const int m0   = blockIdx.y * 128;
    const int n0   = blockIdx.x * 128;

    // ---- cp.async copy mapping: thread -> (row, 32B half) ----
    const int crow  = tid >> 1;         // 0..127
    const int chalf = tid & 1;          // 0..1
    const uint32_t csw = (uint32_t)((crow & 6) << 3);                 // bits 4..5
    const uint32_t cd0 = (uint32_t)(crow * 64) + (((uint32_t)(chalf * 32) + 0u)  ^ csw);
    const uint32_t cd1 = (uint32_t)(crow * 64) + (((uint32_t)(chalf * 32) + 16u) ^ csw);

    const __nv_bfloat16* gAh = Ah + (size_t)(m0 + crow) * lda + chalf * 16;
    const __nv_bfloat16* gAl = Al + (size_t)(m0 + crow) * lda + chalf * 16;
    const __nv_bfloat16* gBh = Bh + (size_t)(n0 + crow) * K   + chalf * 16;
    const __nv_bfloat16* gBl = Bl + (size_t)(n0 + crow) * K   + chalf * 16;

    // ---- ldmatrix fragment addressing ----
    const int g  = lane >> 3;
    const int l8 = lane & 7;
    const uint32_t fsw = (uint32_t)((l8 & 6) << 3);   // row-derived swizzle (rows +8/+16 keep bits 1..2)
    // A mats: (g&1)->m+8, (g>>1)->k chunk16
    const uint32_t a_row = (uint32_t)(wm * 64 + (g & 1) * 8 + l8);
    // B mats: (g>>1)->n+8, (g&1)->k chunk16
    const uint32_t b_row = (uint32_t)(wn * 32 + (g >> 1) * 8 + l8);
    // per-ka in-row chunk offsets: XOR applied to the FULL logical offset
    uint32_t aCk[2], bCk[2];
    #pragma unroll
    for (int ka = 0; ka < 2; ++ka) {
        aCk[ka] = ((uint32_t)((g >> 1) * 16 + ka * 32)) ^ fsw;
        bCk[ka] = ((uint32_t)((g & 1)  * 16 + ka * 32)) ^ fsw;
    }
    const uint32_t aBase = a_row * 64u;             // + region + i*1024 + aCk[ka]
    const uint32_t bBase = b_row * 64u;             // + region + {0,1024} + bCk[ka]

    float acc[4][4][4];
    #pragma unroll
    for (int i = 0; i < 4; ++i)
        #pragma unroll
        for (int j = 0; j < 4; ++j)
            #pragma unroll
            for (int r = 0; r < 4; ++r) acc[i][j][r] = 0.f;

    const int NC = K / BK;

    // prologue: stage chunk 0
    {
        uint32_t st = sb;
        cpasync16(st + cd0,          gAh);
        cpasync16(st + cd1,          gAh + 8);
        cpasync16(st + 8192u  + cd0, gAl);
        cpasync16(st + 8192u  + cd1, gAl + 8);
        cpasync16(st + 16384u + cd0, gBh);
        cpasync16(st + 16384u + cd1, gBh + 8);
        cpasync16(st + 24576u + cd0, gBl);
        cpasync16(st + 24576u + cd1, gBl + 8);
        cp_commit();
    }

    for (int c = 0; c < NC; ++c) {
        if (c > 0) __syncthreads();          // all warps done reading buffer (c+1)&1
        if (c + 1 < NC) {
            const int kc = (c + 1) * BK;
            uint32_t st = sb + (uint32_t)((c + 1) & 1) * STAGE;
            cpasync16(st + cd0,          gAh + kc);
            cpasync16(st + cd1,          gAh + kc + 8);
            cpasync16(st + 8192u  + cd0, gAl + kc);
            cpasync16(st + 8192u  + cd1, gAl + kc + 8);
            cpasync16(st + 16384u + cd0, gBh + kc);
            cpasync16(st + 16384u + cd1, gBh + kc + 8);
            cpasync16(st + 24576u + cd0, gBl + kc);
            cpasync16(st + 24576u + cd1, gBl + kc + 8);
            cp_commit();
            cp_wait1();
        } else {
            cp_wait0();
        }
        __syncthreads();                     // chunk c visible to all

        const uint32_t st = sb + (uint32_t)(c & 1) * STAGE;
        #pragma unroll
        for (int ka = 0; ka < 2; ++ka) {
            uint32_t bh[2][4], bl[2][4];
            ldsm4(bh[0], st + 16384u + bBase +    0u + bCk[ka]);
            ldsm4(bh[1], st + 16384u + bBase + 1024u + bCk[ka]);
            ldsm4(bl[0], st + 24576u + bBase +    0u + bCk[ka]);
            ldsm4(bl[1], st + 24576u + bBase + 1024u + bCk[ka]);
            #pragma unroll
            for (int i = 0; i < 4; ++i) {
                uint32_t af[4], alf[4];
                ldsm4(af,  st +         aBase + (uint32_t)(i * 1024) + aCk[ka]);
                ldsm4(alf, st + 8192u + aBase + (uint32_t)(i * 1024) + aCk[ka]);
                #pragma unroll
                for (int j = 0; j < 4; ++j) {
                    const uint32_t b0h = bh[j >> 1][(j & 1) * 2];
                    const uint32_t b1h = bh[j >> 1][(j & 1) * 2 + 1];
                    const uint32_t b0l = bl[j >> 1][(j & 1) * 2];
                    const uint32_t b1l = bl[j >> 1][(j & 1) * 2 + 1];
                    mma16816(acc[i][j], af,  b0h, b1h);
                    mma16816(acc[i][j], af,  b0l, b1l);
                    mma16816(acc[i][j], alf, b0h, b1h);
                }
            }
        }
    }

    // ---- epilogue ----
    const int quad = lane >> 2;
    const int tq   = lane & 3;
    #pragma unroll
    for (int i = 0; i < 4; ++i) {
        #pragma unroll
        for (int j = 0; j < 4; ++j) {
            const int m = m0 + wm * 64 + i * 16 + quad;
            const int cc = n0 + wn * 32 + j * 8 + tq * 2;
            const float bb0 = __ldg(bias + cc);
            const float bb1 = __ldg(bias + cc + 1);
            if (ACT) {
                float v00 = tanhf(acc[i][j][0] + bb0);
                float v01 = tanhf(acc[i][j][1] + bb1);
                float v10 = tanhf(acc[i][j][2] + bb0);
                float v11 = tanhf(acc[i][j][3] + bb1);
                __nv_bfloat16 h00, l00, h01, l01, h10, l10, h11, l11;
                split_bf16(v00, h00, l00); split_bf16(v01, h01, l01);
                split_bf16(v10, h10, l10); split_bf16(v11, h11, l11);
                __nv_bfloat162 hp0; hp0.x = h00; hp0.y = h01;
                __nv_bfloat162 lp0; lp0.x = l00; lp0.y = l01;
                __nv_bfloat162 hp1; hp1.x = h10; hp1.y = h11;
                __nv_bfloat162 lp1; lp1.x = l10; lp1.y = l11;
                *reinterpret_cast<__nv_bfloat162*>(Ch + (size_t)m * ldc + cc)       = hp0;
                *reinterpret_cast<__nv_bfloat162*>(Cl + (size_t)m * ldc + cc)       = lp0;
                *reinterpret_cast<__nv_bfloat162*>(Ch + (size_t)(m + 8) * ldc + cc) = hp1;
                *reinterpret_cast<__nv_bfloat162*>(Cl + (size_t)(m + 8) * ldc + cc) = lp1;
            } else {
                float2 v0; v0.x = acc[i][j][0] + bb0; v0.y = acc[i][j][1] + bb1;
                float2 v1; v1.x = acc[i][j][2] + bb0; v1.y = acc[i][j][3] + bb1;
                *reinterpret_cast<float2*>(Cf + (size_t)m * ldc + cc)       = v0;
                *reinterpret_cast<float2*>(Cf + (size_t)(m + 8) * ldc + cc) = v1;
            }
        }
    }
}

// ---------------------------------------------------------------------------
// K5: per-row epilogue
// ---------------------------------------------------------------------------
__global__ void final_kernel(const float* __restrict__ z,
                             const float* __restrict__ inv_mass,
                             const float* __restrict__ diffusion,
                             float* __restrict__ out)
{
    int row = blockIdx.x;
    int j   = threadIdx.x;

    float p1  = g_P1[(long)row * LD + j];
    float p2  = g_P2[(long)row * LD + j];
    float dif = diffusion[j];

    float sgn  = (dif > 0.f) ? 1.f : ((dif < 0.f) ? -1.f : 0.f);
    float sden = (fabsf(dif) > 1e-7f) ? dif : sgn * 1e-7f;
    float r    = (p1 - p2) / sden;
    float sq   = r * r;

    __shared__ float wsum[8];
    #pragma unroll
    for (int off = 16; off > 0; off >>= 1)
        sq += __shfl_down_sync(0xffffffffu, sq, off);
    if ((j & 31) == 0) wsum[j >> 5] = sq;
    __syncthreads();

    long dbase = (long)row * OUTC;
    long obase = (long)NB * OUTC + dbase;

    if (j == 0) {
        float s = 0.f;
        #pragma unroll
        for (int w = 0; w < 8; ++w) s += wsum[w];
        out[dbase + 512] = s;
        out[obase + 512] = 0.f;
    }
    float mom = z[(long)row * ZLD + 256 + j];
    out[dbase + j]       = inv_mass[j] * mom;
    out[dbase + 256 + j] = p2;
    out[obase + j]       = 0.f;
    out[obase + 256 + j] = dif;
}

// ---------------------------------------------------------------------------
extern "C" void kernel_launch(void* const* d_in, const int* in_sizes, int n_in,
                              void* d_out, int out_size)
{
    const float* z    = (const float*)d_in[0];
    const float* ts   = (const float*)d_in[1];
    const float* t    = (const float*)d_in[2];
    const float* ctx  = (const float*)d_in[3];
    const float* im   = (const float*)d_in[4];
    const float* dif  = (const float*)d_in[5];
    const float* Wc1  = (const float*)d_in[6];
    const float* bc1  = (const float*)d_in[7];
    const float* Wc2  = (const float*)d_in[8];
    const float* bc2  = (const float*)d_in[9];
    const float* Wh1  = (const float*)d_in[10];
    const float* bh1  = (const float*)d_in[11];
    const float* Wh2  = (const float*)d_in[12];
    const float* bh2  = (const float*)d_in[13];
    float* out = (float*)d_out;

    __nv_bfloat16 *pXh, *pXl, *pH1h, *pH1l, *pH2h, *pH2l;
    __nv_bfloat16 *pWh1h, *pWh1l, *pWc1h, *pWc1l, *pWh2h, *pWh2l, *pWc2h, *pWc2l;
    float *pP1, *pP2;
    cudaGetSymbolAddress((void**)&pXh,  g_Xh);   cudaGetSymbolAddress((void**)&pXl,  g_Xl);
    cudaGetSymbolAddress((void**)&pH1h, g_H1h);  cudaGetSymbolAddress((void**)&pH1l, g_H1l);
    cudaGetSymbolAddress((void**)&pH2h, g_H2h);  cudaGetSymbolAddress((void**)&pH2l, g_H2l);
    cudaGetSymbolAddress((void**)&pP1,  g_P1);   cudaGetSymbolAddress((void**)&pP2,  g_P2);
    cudaGetSymbolAddress((void**)&pWh1h, g_Wh1h); cudaGetSymbolAddress((void**)&pWh1l, g_Wh1l);
    cudaGetSymbolAddress((void**)&pWc1h, g_Wc1h); cudaGetSymbolAddress((void**)&pWc1l, g_Wc1l);
    cudaGetSymbolAddress((void**)&pWh2h, g_Wh2h); cudaGetSymbolAddress((void**)&pWh2l, g_Wh2l);
    cudaGetSymbolAddress((void**)&pWc2h, g_Wc2h); cudaGetSymbolAddress((void**)&pWc2l, g_Wc2l);

    const int smem_bytes = 2 * STAGE;   // 64 KB
    cudaFuncSetAttribute(mma_gemm<1>, cudaFuncAttributeMaxDynamicSharedMemorySize, smem_bytes);
    cudaFuncSetAttribute(mma_gemm<0>, cudaFuncAttributeMaxDynamicSharedMemorySize, smem_bytes);

    // weight prep (transpose + split)
    wsplit_kernel<<<dim3(HD / 32, 512 / 32), dim3(32, 32)>>>(Wh1, 512, HD, pWh1h, pWh1l);
    wsplit_kernel<<<dim3(HD / 32, XK  / 32), dim3(32, 32)>>>(Wc1, XK,  HD, pWc1h, pWc1l);
    wsplit_kernel<<<dim3(LD / 32, HD  / 32), dim3(32, 32)>>>(Wh2, HD,  LD, pWh2h, pWh2l);
    wsplit_kernel<<<dim3(LD / 32, HD  / 32), dim3(32, 32)>>>(Wc2, HD,  LD, pWc2h, pWc2l);

    // X build (bf16 hi/lo)
    prep_kernel<<<(NB * XK) / 256, 256>>>(z, ctx, ts, t);

    // H1 = tanh(pm @ Wh1 + bh1)   K=512 (first 512 cols of X)
    mma_gemm<1><<<dim3(HD / 128, NB / 128), 256, smem_bytes>>>(
        pXh, pXl, XK, pWh1h, pWh1l, bh1, pH1h, pH1l, nullptr, HD, 512);
    // H2 = tanh(X @ Wc1 + bc1)    K=1024
    mma_gemm<1><<<dim3(HD / 128, NB / 128), 256, smem_bytes>>>(
        pXh, pXl, XK, pWc1h, pWc1l, bc1, pH2h, pH2l, nullptr, HD, 1024);
    // P1 = H1 @ Wh2 + bh2         N=256
    mma_gemm<0><<<dim3(LD / 128, NB / 128), 256, smem_bytes>>>(
        pH1h, pH1l, HD, pWh2h, pWh2l, bh2, nullptr, nullptr, pP1, LD, 1024);
    // P2 = H2 @ Wc2 + bc2
    mma_gemm<0><<<dim3(LD / 128, NB / 128), 256, smem_bytes>>>(
        pH2h, pH2l, HD, pWc2h, pWc2l, bc2, nullptr, nullptr, pP2, LD, 1024);

    final_kernel<<<NB, 256>>>(z, im, dif, out);
}